// round 15
// baseline (speedup 1.0000x reference)
#include <cuda_runtime.h>

#define HID 1024
#define NSAMP 1024
#define TSTEPS 98
#define G 4            // samples per CTA
#define NTHR 256       // threads per CTA
#define NCTA (NSAMP / G)

__device__ float g_W2J[HID * HID];  // [src h][reordered dest col]
__device__ float g_W3J[HID * HID];
__device__ int g_u2[HID];           // col -> dest unit (layer 2 ordering)
__device__ int g_u3[HID];           // col -> dest unit (layer 3 ordering)
__device__ int g_S2[99];            // group prefix sums (98 groups)
__device__ int g_S3[2][50];         // per-parity group prefix sums
__device__ float g_fr[3];

// ---------------------------------------------------------------------------
__global__ void init_tables() {
    if (threadIdx.x != 0 || blockIdx.x != 0) return;
    int s = 0;
    for (int g = 0; g < 98; g++) {
        g_S2[g] = s;
        int rho = (3 * g) % 98;
        int cnt = (rho < 44) ? 11 : 10;
        for (int i = 0; i < cnt; i++) g_u2[s + i] = rho + 98 * i;
        s += cnt;
    }
    g_S2[98] = s;
    for (int p = 0; p < 2; p++) {
        int sp = 512 * p;
        for (int g3 = 0; g3 < 49; g3++) {
            g_S3[p][g3] = sp;
            int q = (2 * g3) % 49;
            int rho = 2 * q + p;
            int cnt = (rho < 44) ? 11 : 10;
            for (int i = 0; i < cnt; i++) g_u3[sp + i] = rho + 98 * i;
            sp += cnt;
        }
        g_S3[p][49] = sp;
    }
    g_fr[0] = 0.0f; g_fr[1] = 0.0f; g_fr[2] = 0.0f;
}

// ---------------------------------------------------------------------------
__global__ void prep_kernel(const float* __restrict__ W2,
                            const float* __restrict__ W3) {
    __shared__ float tile[32][33];
    __shared__ int uu[32];
    const float* src = (blockIdx.z == 0) ? W2 : W3;
    float* dst = (blockIdx.z == 0) ? g_W2J : g_W3J;
    const int* umap = (blockIdx.z == 0) ? g_u2 : g_u3;
    int c0 = blockIdx.x * 32, h0 = blockIdx.y * 32;
    int tx = threadIdx.x, ty = threadIdx.y;
    if (ty == 0) uu[tx] = umap[c0 + tx];
    __syncthreads();
    tile[ty][tx] = src[uu[ty] * HID + h0 + tx];
    __syncthreads();
    dst[(h0 + ty) * HID + c0 + tx] = tile[tx][ty];
}

// ---------------------------------------------------------------------------
static __device__ __forceinline__ unsigned long long addf32x2(
    unsigned long long a, unsigned long long b) {
    unsigned long long o;
    asm("add.rn.f32x2 %0, %1, %2;" : "=l"(o) : "l"(a), "l"(b));
    return o;
}

static __device__ __forceinline__ unsigned spread4(unsigned m) {
    return ((m & 0xFu) * 0x00204081u) & 0x01010101u;
}

static __device__ __forceinline__ unsigned bytesum(unsigned v, unsigned c) {
    unsigned ones = 0x01010101u;
    unsigned r;
    asm("dp4a.u32.u32 %0, %1, %2, %3;" : "=r"(r) : "r"(v), "r"(ones), "r"(c));
    return r;
}

// exclusive scan over 256 threads (8 warps)
static __device__ __forceinline__ void block_scan(int v, int tid, int* s_warp,
                                                  int& excl, int& total) {
    int lane = tid & 31, wid = tid >> 5;
    int x = v;
#pragma unroll
    for (int o = 1; o < 32; o <<= 1) {
        int y = __shfl_up_sync(0xffffffffu, x, o);
        if (lane >= o) x += y;
    }
    __syncthreads();
    if (lane == 31) s_warp[wid] = x;
    __syncthreads();
    int pre = 0, tot = 0;
#pragma unroll
    for (int w = 0; w < 8; w++) {
        int sw = s_warp[w];
        pre += (w < wid) ? sw : 0;
        tot += sw;
    }
    excl = pre + x - v;
    total = tot;
}

union F2U { unsigned long long u; float2 f; };

// one row, one column pair: 4 mask tests, predicated packed adds
#define ACC1(e, v)                                              \
    do {                                                        \
        unsigned _m = (e) >> 10;                                \
        if (_m & 1u) acc[0] = addf32x2(acc[0], (v));            \
        if (_m & 2u) acc[1] = addf32x2(acc[1], (v));            \
        if (_m & 4u) acc[2] = addf32x2(acc[2], (v));            \
        if (_m & 8u) acc[3] = addf32x2(acc[3], (v));            \
    } while (0)

// gather a run of rows into acc (no init), single column-pair pointer,
// depth-4 weight pipeline; list offset may be unaligned -> scalar reads
static __device__ __forceinline__ void gather_run(
    const unsigned* __restrict__ list, int n,
    const unsigned long long* __restrict__ p, unsigned long long* acc) {
    int i = 0;
    if (n >= 4) {
        unsigned e0 = list[0], e1 = list[1], e2 = list[2], e3 = list[3];
        unsigned long long w0 = __ldg(p + ((e0 & 1023u) << 9));
        unsigned long long w1 = __ldg(p + ((e1 & 1023u) << 9));
        unsigned long long w2 = __ldg(p + ((e2 & 1023u) << 9));
        unsigned long long w3 = __ldg(p + ((e3 & 1023u) << 9));
        while (true) {
            unsigned f0 = e0, f1 = e1, f2 = e2, f3 = e3;
            unsigned long long v0 = w0, v1 = w1, v2 = w2, v3 = w3;
            i += 4;
            bool more = (i + 4 <= n);
            if (more) {
                e0 = list[i]; e1 = list[i + 1];
                e2 = list[i + 2]; e3 = list[i + 3];
                w0 = __ldg(p + ((e0 & 1023u) << 9));
                w1 = __ldg(p + ((e1 & 1023u) << 9));
                w2 = __ldg(p + ((e2 & 1023u) << 9));
                w3 = __ldg(p + ((e3 & 1023u) << 9));
            }
            ACC1(f0, v0);
            ACC1(f1, v1);
            ACC1(f2, v2);
            ACC1(f3, v3);
            if (!more) break;
        }
    }
    for (; i < n; i++) {
        unsigned e = list[i];
        unsigned long long v = __ldg(p + ((e & 1023u) << 9));
        ACC1(e, v);
    }
}

// balanced worker phase: warp wid takes global work slice of (region, row)
// items; writes zero-based partials to part[(wid*2+slot)*32+lane][4]
static __device__ __forceinline__ void balanced_gather(
    unsigned mask, const unsigned* __restrict__ list, int cnt,
    const unsigned long long* __restrict__ W,
    unsigned long long* __restrict__ part, int wid, int lane) {
    if (cnt <= 0) return;
    int nact = __popc(mask);
    int T = nact * cnt;
    int s = (wid * T) >> 3, e = ((wid + 1) * T) >> 3;
    if (s >= e) return;
    int a = s / cnt, slot = 0, j = s;
    while (j < e) {
        int r = __fns(mask, 0, a + 1);
        const unsigned long long* pr = W + r * 32 + lane;
        int r0 = j - a * cnt;
        int rend = e - a * cnt;
        if (rend > cnt) rend = cnt;
        unsigned long long acc[G] = {0, 0, 0, 0};
        gather_run(list + r0, rend - r0, pr, acc);
        unsigned long long* dst = part + (((wid << 1) + slot) * 32 + lane) * 4;
        dst[0] = acc[0]; dst[1] = acc[1]; dst[2] = acc[2]; dst[3] = acc[3];
        j = a * cnt + rend;
        a++;
        slot++;
    }
}

// owner phase: add the (<=3) chunk partials covering region r, w-ascending
static __device__ __forceinline__ void collect_pair(
    unsigned mask, int cnt, const unsigned long long* __restrict__ part,
    int r, int lane, unsigned long long* acc) {
    if (cnt <= 0 || !(mask & (1u << r))) return;
    int nact = __popc(mask);
    int T = nact * cnt;
    int ar = __popc(mask & ((1u << r) - 1u));
    int arc0 = ar * cnt, arc1 = arc0 + cnt;
#pragma unroll
    for (int w = 0; w < 8; w++) {
        int sw = (w * T) >> 3, ew = ((w + 1) * T) >> 3;
        if (sw < ew && sw < arc1 && ew > arc0) {
            int slot = ar - sw / cnt;
            const unsigned long long* src =
                part + (((w << 1) + slot) * 32 + lane) * 4;
            acc[0] = addf32x2(acc[0], src[0]);
            acc[1] = addf32x2(acc[1], src[1]);
            acc[2] = addf32x2(acc[2], src[2]);
            acc[3] = addf32x2(acc[3], src[3]);
        }
    }
}

// ---------------------------------------------------------------------------
__global__ void __launch_bounds__(NTHR, 2) snn_kernel(
    const float* __restrict__ input,
    const float* __restrict__ W1, const float* __restrict__ b1,
    const float* __restrict__ b2, const float* __restrict__ b3,
    const float* __restrict__ W4, const float* __restrict__ b4,
    float* __restrict__ out) {
    __shared__ __align__(16) unsigned listA[512];
    __shared__ __align__(16) unsigned listB[512];
    __shared__ int s_warp[8];
    __shared__ float xsh[G * 8];
    __shared__ float4 s_red4[8];
    __shared__ __align__(16) ulonglong2 dcsh[G * NTHR];  // const L1 drive
    __shared__ __align__(16) unsigned long long part[8 * 2 * 32 * 4];  // 16KB

    const int tid = threadIdx.x;
    const int lane = tid & 31, wid = tid >> 5;
    const int n0 = blockIdx.x * G;
    const int h0 = 4 * tid;  // layer-1 units

    // col maps: slot k -> col c = 512*(k>>1) + 2*tid + (k&1)
    int h2s[4], h3s[4];
    float b2v[4], b3v[4];
#pragma unroll
    for (int k = 0; k < 4; k++) {
        int c = 512 * (k >> 1) + 2 * tid + (k & 1);
        h2s[k] = __ldg(&g_u2[c]);
        h3s[k] = __ldg(&g_u3[c]);
        b2v[k] = __ldg(b2 + h2s[k]);
        b3v[k] = __ldg(b3 + h3s[k]);
    }
    unsigned long long bp2L, bp2H, bp3L, bp3H;
    {
        F2U a, b, c, d;
        a.f = make_float2(b2v[0], b2v[1]); bp2L = a.u;
        b.f = make_float2(b2v[2], b2v[3]); bp2H = b.u;
        c.f = make_float2(b3v[0], b3v[1]); bp3L = c.u;
        d.f = make_float2(b3v[2], b3v[3]); bp3H = d.u;
    }

    float m1[4][G], m2[4][G], m3[4][G];
#pragma unroll
    for (int k = 0; k < 4; k++)
#pragma unroll
        for (int g = 0; g < G; g++) {
            m1[k][g] = 0.f; m2[k][g] = 0.f; m3[k][g] = 0.f;
        }
    unsigned ss1[4] = {0,0,0,0}, ss2[4] = {0,0,0,0}, ss3[4] = {0,0,0,0};

    const float4* W14 = reinterpret_cast<const float4*>(W1);
    const unsigned long long* Wu2 =
        reinterpret_cast<const unsigned long long*>(g_W2J);
    const unsigned long long* Wu3 =
        reinterpret_cast<const unsigned long long*>(g_W3J);

    // constant layer-1 drive (t >= 12 uses input slice at 776)
    if (tid < G * 8)
        xsh[tid] = __ldg(input + (n0 + (tid >> 3)) * 784 + 776 + (tid & 7));
    __syncthreads();
    {
        float4 bq1 = __ldg(reinterpret_cast<const float4*>(b1) + tid);
        float w1r[4][8];
#pragma unroll
        for (int k = 0; k < 4; k++) {
            float4 a = __ldg(W14 + (h0 + k) * 2);
            float4 c = __ldg(W14 + (h0 + k) * 2 + 1);
            w1r[k][0] = a.x; w1r[k][1] = a.y; w1r[k][2] = a.z; w1r[k][3] = a.w;
            w1r[k][4] = c.x; w1r[k][5] = c.y; w1r[k][6] = c.z; w1r[k][7] = c.w;
        }
        float bb[4] = {bq1.x, bq1.y, bq1.z, bq1.w};
#pragma unroll
        for (int g = 0; g < G; g++) {
            const float* x = &xsh[g * 8];
            float s[4];
#pragma unroll
            for (int k = 0; k < 4; k++) {
                float acc = bb[k];
#pragma unroll
                for (int i = 0; i < 8; i++) acc += x[i] * w1r[k][i];
                s[k] = acc;
            }
            F2U lo, hi;
            lo.f = make_float2(s[0], s[1]);
            hi.f = make_float2(s[2], s[3]);
            dcsh[g * NTHR + tid] = make_ulonglong2(lo.u, hi.u);
        }
    }
    __syncthreads();

    int w0 = 66;    // (33*t + 66) % 98 at t=0
    int g3lo = 25;  // (25*tau + 25) % 49 at tau=0

    for (int t = 0; t < TSTEPS; t++) {
        const int par = t & 1;

        // ---------- layer 1 drive ----------
        unsigned long long d1L[G], d1H[G];
        if (t < 12) {
            if (tid < G * 8)
                xsh[tid] =
                    __ldg(input + (n0 + (tid >> 3)) * 784 + t * 8 + (tid & 7));
            __syncthreads();
            float4 bq1 = __ldg(reinterpret_cast<const float4*>(b1) + tid);
            float w1r[4][8];
#pragma unroll
            for (int k = 0; k < 4; k++) {
                float4 a = __ldg(W14 + (h0 + k) * 2);
                float4 c = __ldg(W14 + (h0 + k) * 2 + 1);
                w1r[k][0] = a.x; w1r[k][1] = a.y; w1r[k][2] = a.z; w1r[k][3] = a.w;
                w1r[k][4] = c.x; w1r[k][5] = c.y; w1r[k][6] = c.z; w1r[k][7] = c.w;
            }
            float bb[4] = {bq1.x, bq1.y, bq1.z, bq1.w};
#pragma unroll
            for (int g = 0; g < G; g++) {
                const float* x = &xsh[g * 8];
                float s[4];
#pragma unroll
                for (int k = 0; k < 4; k++) {
                    float acc = bb[k];
#pragma unroll
                    for (int i = 0; i < 8; i++) acc += x[i] * w1r[k][i];
                    s[k] = acc;
                }
                F2U lo, hi;
                lo.f = make_float2(s[0], s[1]);
                hi.f = make_float2(s[2], s[3]);
                d1L[g] = lo.u;
                d1H[g] = hi.u;
            }
            __syncthreads();
        } else {
#pragma unroll
            for (int g = 0; g < G; g++) {
                ulonglong2 v = dcsh[g * NTHR + tid];
                d1L[g] = v.x;
                d1H[g] = v.y;
            }
        }

        // ---------- layer 1 update (eligible k = par, par+2) ----------
        unsigned mk0 = 0, mk2 = 0;
        if (par == 0) {
#pragma unroll
            for (int g = 0; g < G; g++) {
                F2U uL, uH; uL.u = d1L[g]; uH.u = d1H[g];
                float na = m1[0][g] * 0.5f + uL.f.x;
                float nc = m1[2][g] * 0.5f + uH.f.x;
                m1[0][g] = na; m1[2][g] = nc;
                if (na > 0.5f) mk0 |= 1u << g;
                if (nc > 0.5f) mk2 |= 1u << g;
            }
            ss1[0] += spread4(mk0);
            ss1[2] += spread4(mk2);
        } else {
#pragma unroll
            for (int g = 0; g < G; g++) {
                F2U uL, uH; uL.u = d1L[g]; uH.u = d1H[g];
                float na = m1[1][g] * 0.5f + uL.f.y;
                float nc = m1[3][g] * 0.5f + uH.f.y;
                m1[1][g] = na; m1[3][g] = nc;
                if (na > 0.5f) mk0 |= 1u << g;
                if (nc > 0.5f) mk2 |= 1u << g;
            }
            ss1[1] += spread4(mk0);
            ss1[3] += spread4(mk2);
        }

        int excl, cntA;
        block_scan((mk0 ? 1 : 0) + (mk2 ? 1 : 0), tid, s_warp, excl, cntA);
        {
            int p = excl;
            if (mk0) listA[p++] = (mk0 << 10) | (unsigned)(h0 + par);
            if (mk2) listA[p] = (mk2 << 10) | (unsigned)(h0 + par + 2);
        }
        __syncthreads();

        // ---------- layer 2: balanced gather + update ----------
        int cntB;
        {
            int lo = __ldg(&g_S2[w0]);
            int hiI = w0 + 33;
            bool wrap = hiI > 98;
            int hi = wrap ? __ldg(&g_S2[hiI - 98]) : __ldg(&g_S2[hiI]);
            unsigned mask = 0;
#pragma unroll
            for (int r = 0; r < 16; r++) {
                int cl = 64 * r, ch = cl + 64;
                bool act = wrap ? (cl < hi || ch > lo) : (ch > lo && cl < hi);
                if (act) mask |= 1u << r;
            }
            balanced_gather(mask, listA, cntA, Wu2, part, wid, lane);
            __syncthreads();

            unsigned long long accA[G], accB[G];
#pragma unroll
            for (int g = 0; g < G; g++) { accA[g] = bp2L; accB[g] = bp2H; }
            collect_pair(mask, cntA, part, wid, lane, accA);
            collect_pair(mask, cntA, part, wid + 8, lane, accB);

            unsigned msk[4];
            int cl = 0;
#pragma unroll
            for (int k = 0; k < 4; k++) {
                int c = 512 * (k >> 1) + 2 * tid + (k & 1);
                bool el = wrap ? (c >= lo || c < hi) : (c >= lo && c < hi);
                msk[k] = 0;
                if (el) {
                    unsigned mm = 0;
#pragma unroll
                    for (int g = 0; g < G; g++) {
                        F2U u;
                        u.u = (k >> 1) ? accB[g] : accA[g];
                        float d = (k & 1) ? u.f.y : u.f.x;
                        float nm = m2[k][g] * 0.5f + d;
                        m2[k][g] = nm;
                        if (nm > 0.5f) mm |= 1u << g;
                    }
                    msk[k] = mm;
                    ss2[k] += spread4(mm);
                    cl += (mm ? 1 : 0);
                }
            }
            block_scan(cl, tid, s_warp, excl, cntB);
            {
                int p = excl;
#pragma unroll
                for (int k = 0; k < 4; k++)
                    if (msk[k]) listB[p++] = (msk[k] << 10) | (unsigned)h2s[k];
            }
            __syncthreads();
        }

        // ---------- layer 3: balanced gather + update ----------
        {
            int lo = __ldg(&g_S3[par][g3lo]);
            int hiI = g3lo + 25;
            bool wrap = hiI > 49;
            int hi = wrap ? __ldg(&g_S3[par][hiI - 49]) : __ldg(&g_S3[par][hiI]);
            unsigned mask = 0;
#pragma unroll
            for (int r = 0; r < 16; r++) {
                int cl = 64 * r, ch = cl + 64;
                bool act = wrap ? (cl < hi || ch > lo) : (ch > lo && cl < hi);
                if (act) mask |= 1u << r;
            }
            mask &= par ? 0xFF00u : 0x00FFu;  // only parity block regions
            balanced_gather(mask, listB, cntB, Wu3, part, wid, lane);
            __syncthreads();

            unsigned long long accA[G], accB[G];
#pragma unroll
            for (int g = 0; g < G; g++) { accA[g] = bp3L; accB[g] = bp3H; }
            collect_pair(mask, cntB, part, wid, lane, accA);
            collect_pair(mask, cntB, part, wid + 8, lane, accB);

#pragma unroll
            for (int k = 0; k < 4; k++) {
                int p = k >> 1;
                int c = 512 * p + 2 * tid + (k & 1);
                bool el = (p == par) &&
                          (wrap ? (c >= lo || c < hi) : (c >= lo && c < hi));
                if (el) {
                    unsigned mm = 0;
#pragma unroll
                    for (int g = 0; g < G; g++) {
                        F2U u;
                        u.u = p ? accB[g] : accA[g];
                        float d = (k & 1) ? u.f.y : u.f.x;
                        float nm = m3[k][g] * 0.5f + d;
                        m3[k][g] = nm;
                        if (nm > 0.5f) mm |= 1u << g;
                    }
                    ss3[k] += spread4(mm);
                }
            }
        }

        // advance windows
        w0 += 33; if (w0 >= 98) w0 -= 98;
        if (par == 1) { g3lo += 25; if (g3lo >= 49) g3lo -= 49; }
        __syncthreads();  // part reuse: L3 owner reads before next L2 writes
    }

    // ------------------------- epilogue -------------------------
    const float inv = 1.0f / 98.0f;

#pragma unroll
    for (int g = 0; g < G; g++) {
        int sh = 8 * g;
        float4 v1 = make_float4((float)((ss1[0] >> sh) & 255u) * inv,
                                (float)((ss1[1] >> sh) & 255u) * inv,
                                (float)((ss1[2] >> sh) & 255u) * inv,
                                (float)((ss1[3] >> sh) & 255u) * inv);
        *reinterpret_cast<float4*>(out + 10240 + (n0 + g) * HID + h0) = v1;
    }
#pragma unroll
    for (int k = 0; k < 4; k++) {
#pragma unroll
        for (int g = 0; g < G; g++) {
            int sh = 8 * g;
            float a2 = (float)((ss2[k] >> sh) & 255u);
            float a3 = (float)((ss3[k] >> sh) & 255u);
            out[10240 + 1048576 + (n0 + g) * HID + h2s[k]] = a2 * inv;
            out[10240 + 2097152 + (n0 + g) * HID + h3s[k]] = a3 * inv;
        }
    }

    float s3f[4][G];
#pragma unroll
    for (int k = 0; k < 4; k++)
#pragma unroll
        for (int g = 0; g < G; g++)
            s3f[k][g] = (float)((ss3[k] >> (8 * g)) & 255u);

    for (int o = 0; o < 10; o++) {
        float w4s[4];
#pragma unroll
        for (int k = 0; k < 4; k++) w4s[k] = __ldg(W4 + o * HID + h3s[k]);
        float4 v;
        v.x = s3f[0][0] * w4s[0] + s3f[1][0] * w4s[1] +
              s3f[2][0] * w4s[2] + s3f[3][0] * w4s[3];
        v.y = s3f[0][1] * w4s[0] + s3f[1][1] * w4s[1] +
              s3f[2][1] * w4s[2] + s3f[3][1] * w4s[3];
        v.z = s3f[0][2] * w4s[0] + s3f[1][2] * w4s[1] +
              s3f[2][2] * w4s[2] + s3f[3][2] * w4s[3];
        v.w = s3f[0][3] * w4s[0] + s3f[1][3] * w4s[1] +
              s3f[2][3] * w4s[2] + s3f[3][3] * w4s[3];
#pragma unroll
        for (int off = 16; off > 0; off >>= 1) {
            v.x += __shfl_down_sync(0xffffffffu, v.x, off);
            v.y += __shfl_down_sync(0xffffffffu, v.y, off);
            v.z += __shfl_down_sync(0xffffffffu, v.z, off);
            v.w += __shfl_down_sync(0xffffffffu, v.w, off);
        }
        if (lane == 0) s_red4[wid] = v;
        __syncthreads();
        if (tid == 0) {
            float4 s = make_float4(0, 0, 0, 0);
#pragma unroll
            for (int w = 0; w < 8; w++) {
                s.x += s_red4[w].x; s.y += s_red4[w].y;
                s.z += s_red4[w].z; s.w += s_red4[w].w;
            }
            float bo = __ldg(b4 + o);
            out[(n0 + 0) * 10 + o] = s.x / 98.0f + bo;
            out[(n0 + 1) * 10 + o] = s.y / 98.0f + bo;
            out[(n0 + 2) * 10 + o] = s.z / 98.0f + bo;
            out[(n0 + 3) * 10 + o] = s.w / 98.0f + bo;
        }
        __syncthreads();
    }

    unsigned c1 = 0, c2 = 0, c3 = 0;
#pragma unroll
    for (int k = 0; k < 4; k++) {
        c1 = bytesum(ss1[k], c1);
        c2 = bytesum(ss2[k], c2);
        c3 = bytesum(ss3[k], c3);
    }
    {
        float4 v = make_float4((float)c1, (float)c2, (float)c3, 0.0f);
#pragma unroll
        for (int off = 16; off > 0; off >>= 1) {
            v.x += __shfl_down_sync(0xffffffffu, v.x, off);
            v.y += __shfl_down_sync(0xffffffffu, v.y, off);
            v.z += __shfl_down_sync(0xffffffffu, v.z, off);
        }
        if (lane == 0) s_red4[wid] = v;
        __syncthreads();
        if (tid == 0) {
            float s0 = 0, s1 = 0, s2 = 0;
#pragma unroll
            for (int w = 0; w < 8; w++) {
                s0 += s_red4[w].x; s1 += s_red4[w].y; s2 += s_red4[w].z;
            }
            atomicAdd(&g_fr[0], s0);
            atomicAdd(&g_fr[1], s1);
            atomicAdd(&g_fr[2], s2);
        }
    }
}

__global__ void finalize_kernel(float* __restrict__ out) {
    if (threadIdx.x < 3)
        out[3155968 + threadIdx.x] = g_fr[threadIdx.x] / 102760448.0f;
}

extern "C" void kernel_launch(void* const* d_in, const int* in_sizes, int n_in,
                              void* d_out, int out_size) {
    const float* input = (const float*)d_in[0];
    const float* W1 = (const float*)d_in[1];
    const float* b1 = (const float*)d_in[2];
    const float* W2 = (const float*)d_in[3];
    const float* b2 = (const float*)d_in[4];
    const float* W3 = (const float*)d_in[5];
    const float* b3 = (const float*)d_in[6];
    const float* W4 = (const float*)d_in[7];
    const float* b4 = (const float*)d_in[8];
    (void)in_sizes; (void)n_in; (void)out_size;

    init_tables<<<1, 1>>>();
    dim3 pgrid(HID / 32, HID / 32, 2);
    prep_kernel<<<pgrid, dim3(32, 32)>>>(W2, W3);
    snn_kernel<<<NCTA, NTHR>>>(input, W1, b1, b2, b3, W4, b4, (float*)d_out);
    finalize_kernel<<<1, 32>>>((float*)d_out);
}